// round 8
// baseline (speedup 1.0000x reference)
#include <cuda_runtime.h>
#include <cuda_bf16.h>

// SppPooling: GRID=16, K_MAX=32, D=256, R=256 cells/batch, xy rows = 35 int32
#define GRIDSZ 16
#define RCELLS (GRIDSZ * GRIDSZ)   // 256
#define KMAX   32
#define FEAT_D 256
#define FIELDS (3 + KMAX)          // 35 int32 per xy row
#define CELLS_PER_BLK 32
#define CELLS_PER_WARP 4           // 8 warp-pairs * 4 = 32 cells
#define NTHREADS 512
#define TSTRIDE4 65                // float4 stride for transpose buffer (pad)

__device__ __forceinline__ void add4(float4& a, const float4& v) {
    a.x += v.x; a.y += v.y; a.z += v.z; a.w += v.w;
}

// ---------------------------------------------------------------------------
// Block = (cell-group g = blockIdx.x in 0..7, batch b = blockIdx.y), 512 thr.
// Warp pair (2p, 2p+1) covers one cell's 256 features (each warp 128 feats,
// 1x LDG.128 per row). 8-row batches with predicated-masked adds:
// ceil(cnt/8) latency-waits per cell (avg 2.5) instead of ~5.1.
//
// Phase 0: block scans 256 header rows -> cell->r map (fused, no pre-kernels).
// Phase 1: metadata (count + 32 inds) for 32 cells -> smem.
// Phase 2: gather+pool, 8 LDG.128 in flight per thread per batch.
// Phase 3: smem transpose -> warp writes 32 consecutive cells per d
//          (128B fully-coalesced stores).
// ---------------------------------------------------------------------------
__global__ __launch_bounds__(NTHREADS, 2)
void spp_pool_kernel(const float* __restrict__ F,
                     const int* __restrict__ xy,
                     float* __restrict__ out,
                     int n_per) {
    const int g    = blockIdx.x;          // 0..7 cell group
    const int b    = blockIdx.y;          // batch
    const int tid  = threadIdx.x;         // 0..511
    const int w    = tid >> 5;            // warp 0..15
    const int lane = tid & 31;

    __shared__ int    s_r[CELLS_PER_BLK];
    __shared__ int    s_cnt[CELLS_PER_BLK];
    __shared__ int    s_ind[CELLS_PER_BLK][KMAX];
    __shared__ float4 s_t4[CELLS_PER_BLK][TSTRIDE4];   // [cell][f4col], 33.3KB

    const int* xyb = xy + (size_t)b * n_per * FIELDS;

    // ---- Phase 0: find source row r for each of this block's 32 cells ----
    if (tid < CELLS_PER_BLK) s_r[tid] = -1;
    __syncthreads();
    if (tid < RCELLS) {
        const int* row = xyb + (size_t)tid * FIELDS;   // r = tid scans headers
        int rr = row[0];
        if (rr >= 0) {
            int cell = rr * GRIDSZ + row[1];
            int c = cell - g * CELLS_PER_BLK;
            if (c >= 0 && c < CELLS_PER_BLK) s_r[c] = tid;
        }
    }
    __syncthreads();

    // ---- Phase 1: metadata (count + 32 indices) for 32 cells ----
    for (int e = tid; e < CELLS_PER_BLK * (KMAX + 1); e += NTHREADS) {
        int c = e / (KMAX + 1);
        int f = e % (KMAX + 1);
        int r = s_r[c];
        int v = 0;
        if (r >= 0) v = xyb[(size_t)r * FIELDS + 2 + f];
        if (f == 0) s_cnt[c] = v;
        else        s_ind[c][f - 1] = v;
    }
    __syncthreads();

    // ---- Phase 2: accumulate. Warp pair p=w>>1 owns cells p*4..p*4+3;
    //      this warp covers float4 columns f4col = (w&1)*32 + lane.
    const float4* __restrict__ Fb =
        (const float4*)(F + (size_t)b * n_per * FEAT_D);
    const int f4col = ((w & 1) << 5) + lane;           // 0..63

    #pragma unroll
    for (int cc = 0; cc < CELLS_PER_WARP; cc++) {
        const int c   = (w >> 1) * CELLS_PER_WARP + cc;
        const int cnt = s_cnt[c];

        float4 acc = make_float4(0.f, 0.f, 0.f, 0.f);

        #pragma unroll 1
        for (int k = 0; k < cnt; k += 8) {
            const int rem = cnt - k;                   // >= 1
            // 8 independent LDG.128 issued up front (indices beyond cnt are
            // valid in-range values; their adds are masked below).
            float4 v[8];
            #pragma unroll
            for (int j = 0; j < 8; j++)
                v[j] = Fb[(size_t)s_ind[c][k + j] * (FEAT_D / 4) + f4col];
            #pragma unroll
            for (int j = 0; j < 8; j++)
                if (j < rem) add4(acc, v[j]);
        }

        const float scal = 1.0f / (float)(cnt > 1 ? cnt : 1);
        float4 r4;
        r4.x = acc.x * scal; r4.y = acc.y * scal;
        r4.z = acc.z * scal; r4.w = acc.w * scal;
        s_t4[c][f4col] = r4;                           // conflict-free
    }
    __syncthreads();

    // ---- Phase 3: transposed coalesced store ----
    // out[b][d][cell]; warp writes 32 consecutive cells for one d (128B).
    const float* s_tf = (const float*)s_t4;   // (c,d) at c*4*TSTRIDE4 + d
    float* __restrict__ ob =
        out + (size_t)b * FEAT_D * RCELLS + g * CELLS_PER_BLK;
    #pragma unroll
    for (int it = 0; it < (FEAT_D * CELLS_PER_BLK) / NTHREADS; it++) { // 16
        int e  = it * NTHREADS + tid;
        int d  = e >> 5;           // 0..255
        int cl = e & 31;           // lane = cell offset
        ob[(size_t)d * RCELLS + cl] = s_tf[cl * (4 * TSTRIDE4) + d];
    }
}

// ---------------------------------------------------------------------------
extern "C" void kernel_launch(void* const* d_in, const int* in_sizes, int n_in,
                              void* d_out, int out_size) {
    const float* F  = (const float*)d_in[0];
    const int*   xy = (const int*)d_in[1];   // int32 (JAX default, no x64)

    int B     = in_sizes[2];                          // 64
    int n_per = in_sizes[0] / (B * FEAT_D);           // 2048
    float* out = (float*)d_out;

    dim3 grid(RCELLS / CELLS_PER_BLK, B);             // (8, 64)
    spp_pool_kernel<<<grid, NTHREADS>>>(F, xy, out, n_per);
}

// round 9
// speedup vs baseline: 1.0078x; 1.0078x over previous
#include <cuda_runtime.h>
#include <cuda_bf16.h>

// SppPooling: GRID=16, K_MAX=32, D=256, R=256 cells/batch, xy rows = 35 int32
#define GRIDSZ 16
#define RCELLS (GRIDSZ * GRIDSZ)   // 256
#define KMAX   32
#define FEAT_D 256
#define FIELDS (3 + KMAX)          // 35 int32 per xy row
#define CELLS_PER_BLK 32
#define CELLS_PER_PAIR 4           // 8 warp-pairs * 4 = 32 cells
#define NTHREADS 512
#define TSTRIDE4 65                // float4 stride for transpose buffer (pad)

__device__ __forceinline__ void add4(float4& a, const float4& v) {
    a.x += v.x; a.y += v.y; a.z += v.z; a.w += v.w;
}

// ---------------------------------------------------------------------------
// Block = (cell-group g, batch b), 512 threads, 3 blocks/SM (48 warps).
// Warp pair (2p,2p+1) covers one cell's 256 features (128 each, 1 LDG.128/row).
// Cells are dealt to warp-pairs by count (bitonic sort + snake deal) so every
// pair does ~mean work instead of the max-of-8 random sum.
// Gather: 4-row batches, remainder rows PREDICATED (no wasted traffic).
// ---------------------------------------------------------------------------
__global__ __launch_bounds__(NTHREADS, 3)
void spp_pool_kernel(const float* __restrict__ F,
                     const int* __restrict__ xy,
                     float* __restrict__ out,
                     int n_per) {
    const int g    = blockIdx.x;          // 0..7 cell group
    const int b    = blockIdx.y;          // batch
    const int tid  = threadIdx.x;         // 0..511
    const int w    = tid >> 5;            // warp 0..15
    const int lane = tid & 31;

    __shared__ int    s_r[CELLS_PER_BLK];
    __shared__ int    s_cnt[CELLS_PER_BLK];
    __shared__ int    s_ind[CELLS_PER_BLK][KMAX];
    __shared__ unsigned char s_ord[CELLS_PER_BLK];     // balanced deal
    __shared__ float4 s_t4[CELLS_PER_BLK][TSTRIDE4];   // 33.3KB transpose buf

    const int* xyb = xy + (size_t)b * n_per * FIELDS;

    // ---- Phase 0: find source row r for each of this block's 32 cells ----
    if (tid < CELLS_PER_BLK) s_r[tid] = -1;
    __syncthreads();
    if (tid < RCELLS) {
        const int* row = xyb + (size_t)tid * FIELDS;   // r = tid scans headers
        int rr = row[0];
        if (rr >= 0) {
            int cell = rr * GRIDSZ + row[1];
            int c = cell - g * CELLS_PER_BLK;
            if (c >= 0 && c < CELLS_PER_BLK) s_r[c] = tid;
        }
    }
    __syncthreads();

    // ---- Phase 1: metadata (count + 32 indices) for 32 cells ----
    for (int e = tid; e < CELLS_PER_BLK * (KMAX + 1); e += NTHREADS) {
        int c = e / (KMAX + 1);
        int f = e % (KMAX + 1);
        int r = s_r[c];
        int v = 0;
        if (r >= 0) v = xyb[(size_t)r * FIELDS + 2 + f];
        if (f == 0) s_cnt[c] = v;
        else        s_ind[c][f - 1] = v;
    }
    __syncthreads();

    // ---- Phase 1.5: balance cells across warp-pairs (warp 0) ----
    // Ascending bitonic sort of (cnt<<8 | cell) via shuffles; snake-deal the
    // descending ranks onto 8 pairs x 4 rounds.
    if (w == 0) {
        unsigned key = ((unsigned)s_cnt[lane] << 8) | (unsigned)lane;
        #pragma unroll
        for (int k2 = 2; k2 <= 32; k2 <<= 1) {
            #pragma unroll
            for (int j = k2 >> 1; j > 0; j >>= 1) {
                unsigned o = __shfl_xor_sync(0xffffffffu, key, j);
                bool dirUp = ((lane & k2) == 0);
                bool lower = ((lane & j)  == 0);
                unsigned mn = key < o ? key : o;
                unsigned mx = key < o ? o : key;
                key = (dirUp == lower) ? mn : mx;   // lane holds asc rank
            }
        }
        int i = 31 - lane;                 // descending rank
        int r = i >> 3, q = i & 7;         // round, position
        int bin = (r & 1) ? (7 - q) : q;   // snake
        s_ord[bin * CELLS_PER_PAIR + r] = (unsigned char)(key & 0xff);
    }
    __syncthreads();

    // ---- Phase 2: accumulate. Warp pair p = w>>1; this warp covers float4
    //      columns f4col = (w&1)*32 + lane (0..63).
    const float4* __restrict__ Fb =
        (const float4*)(F + (size_t)b * n_per * FEAT_D);
    const int f4col = ((w & 1) << 5) + lane;
    const float4 z4 = make_float4(0.f, 0.f, 0.f, 0.f);

    #pragma unroll
    for (int cc = 0; cc < CELLS_PER_PAIR; cc++) {
        const int c   = s_ord[(w >> 1) * CELLS_PER_PAIR + cc];
        const int cnt = s_cnt[c];

        float4 acc = z4;

        #pragma unroll 1
        for (int k = 0; k < cnt; k += 4) {
            const int rem = cnt - k;       // >= 1
            // 4 LDG.128 batched; tail rows predicated off (no extra traffic)
            float4 v0 = Fb[(size_t)(s_ind[c][k + 0] * (FEAT_D / 4) + f4col)];
            float4 v1 = z4, v2 = z4, v3 = z4;
            if (1 < rem) v1 = Fb[(size_t)(s_ind[c][k + 1] * (FEAT_D / 4) + f4col)];
            if (2 < rem) v2 = Fb[(size_t)(s_ind[c][k + 2] * (FEAT_D / 4) + f4col)];
            if (3 < rem) v3 = Fb[(size_t)(s_ind[c][k + 3] * (FEAT_D / 4) + f4col)];
            add4(v0, v1); add4(v2, v3); add4(acc, v0); add4(acc, v2);
        }

        const float scal = 1.0f / (float)(cnt > 1 ? cnt : 1);
        float4 r4;
        r4.x = acc.x * scal; r4.y = acc.y * scal;
        r4.z = acc.z * scal; r4.w = acc.w * scal;
        s_t4[c][f4col] = r4;               // consecutive lanes: conflict-free
    }
    __syncthreads();

    // ---- Phase 3: transposed coalesced store ----
    // out[b][d][cell]; warp writes 32 consecutive cells for one d (128B).
    const float* s_tf = (const float*)s_t4;   // (c,d) at c*4*TSTRIDE4 + d
    float* __restrict__ ob =
        out + (size_t)b * FEAT_D * RCELLS + g * CELLS_PER_BLK;
    #pragma unroll
    for (int it = 0; it < (FEAT_D * CELLS_PER_BLK) / NTHREADS; it++) { // 16
        int e  = it * NTHREADS + tid;
        int d  = e >> 5;           // 0..255
        int cl = e & 31;           // lane = cell offset
        ob[(size_t)d * RCELLS + cl] = s_tf[cl * (4 * TSTRIDE4) + d];
    }
}

// ---------------------------------------------------------------------------
extern "C" void kernel_launch(void* const* d_in, const int* in_sizes, int n_in,
                              void* d_out, int out_size) {
    const float* F  = (const float*)d_in[0];
    const int*   xy = (const int*)d_in[1];   // int32 (JAX default, no x64)

    int B     = in_sizes[2];                          // 64
    int n_per = in_sizes[0] / (B * FEAT_D);           // 2048
    float* out = (float*)d_out;

    dim3 grid(RCELLS / CELLS_PER_BLK, B);             // (8, 64)
    spp_pool_kernel<<<grid, NTHREADS>>>(F, xy, out, n_per);
}